// round 14
// baseline (speedup 1.0000x reference)
#include <cuda_runtime.h>
#include <cuda.h>
#include <cuda_bf16.h>
#include <cstdint>

#define D_EMBED 512
#define N_CLUST 64
#define ROWS_CTA 512
#define NWARP 16
#define X_STAGES 5
#define X_STAGE_BYTES 32768                      // 512 rows x 64B (16 floats)
#define SB_OFF (X_STAGES * X_STAGE_BYTES)        // 163840
#define SC2_OFF (SB_OFF + 65536)                 // 229376
#define SWP_OFF (SC2_OFF + N_CLUST * 4)          // 229632
#define MB_OFF (SWP_OFF + NWARP * 4)             // 229696: F[5] then E[5]
#define SMEM_BYTES (MB_OFF + 10 * 8)             // 229776

// ---------------- device scratch (no allocations allowed) ----------------
__device__ double   g_acc = 0.0;
__device__ unsigned g_ctr = 0;

// ---------------- helpers ----------------
__device__ __forceinline__ unsigned pack_bf16(float lo, float hi) {
    unsigned r;
    asm("cvt.rn.bf16x2.f32 %0, %1, %2;" : "=r"(r) : "f"(hi), "f"(lo));
    return r;
}
__device__ __forceinline__ void mma16816(float* c,
                                         unsigned a0, unsigned a1, unsigned a2, unsigned a3,
                                         unsigned b0, unsigned b1) {
    asm volatile(
        "mma.sync.aligned.m16n8k16.row.col.f32.bf16.bf16.f32 "
        "{%0,%1,%2,%3}, {%4,%5,%6,%7}, {%8,%9}, {%0,%1,%2,%3};"
        : "+f"(c[0]), "+f"(c[1]), "+f"(c[2]), "+f"(c[3])
        : "r"(a0), "r"(a1), "r"(a2), "r"(a3), "r"(b0), "r"(b1));
}
__device__ __forceinline__ float4 lds128(unsigned addr) {
    float4 v;
    asm volatile("ld.shared.v4.f32 {%0,%1,%2,%3}, [%4];"
                 : "=f"(v.x), "=f"(v.y), "=f"(v.z), "=f"(v.w) : "r"(addr));
    return v;
}
__device__ __forceinline__ void mbar_init(unsigned addr, unsigned cnt) {
    asm volatile("mbarrier.init.shared.b64 [%0], %1;" :: "r"(addr), "r"(cnt) : "memory");
}
__device__ __forceinline__ void mbar_arrive(unsigned addr) {
    asm volatile("mbarrier.arrive.release.cta.shared::cta.b64 _, [%0];" :: "r"(addr) : "memory");
}
__device__ __forceinline__ void mbar_expect_tx(unsigned addr, unsigned tx) {
    asm volatile("mbarrier.arrive.expect_tx.shared.b64 _, [%0], %1;" :: "r"(addr), "r"(tx) : "memory");
}
__device__ __forceinline__ void mbar_wait(unsigned addr, unsigned parity) {
    asm volatile(
        "{\n\t.reg .pred P;\n\t"
        "W_%=:\n\t"
        "mbarrier.try_wait.parity.acquire.cta.shared::cta.b64 P, [%0], %1, 0x989680;\n\t"
        "@P bra.uni D_%=;\n\t"
        "bra.uni W_%=;\n\t"
        "D_%=:\n\t}"
        :: "r"(addr), "r"(parity) : "memory");
}
__device__ __forceinline__ void tma2d(unsigned smem_addr, const CUtensorMap* m,
                                      int c0, int c1, unsigned mbar) {
    asm volatile(
        "cp.async.bulk.tensor.2d.shared::cta.global.tile.mbarrier::complete_tx::bytes "
        "[%0], [%1, {%2, %3}], [%4];"
        :: "r"(smem_addr), "l"(m), "r"(c0), "r"(c1), "r"(mbar) : "memory");
}

// alpha may arrive as int32 / int64 / float32 (python scalar 100). Decode robustly.
__device__ __forceinline__ float decode_alpha(const void* p) {
    int iv = *reinterpret_cast<const int*>(p);
    unsigned u = (unsigned)iv;
    unsigned ex = (u >> 23) & 0xffu;
    if (ex >= 110u && ex <= 150u) return __int_as_float(iv);
    if (iv == 0) {
        double dv = *reinterpret_cast<const double*>(p);
        if (dv > 1e-6 && dv < 1e9) return (float)dv;
    }
    return (float)iv;
}

// ---------------- single fused kernel ----------------
__global__ __launch_bounds__(512, 1)
void main_kernel(const float* __restrict__ x, const float* __restrict__ cent,
                 const void* __restrict__ alphap, float* __restrict__ out, int Ntot,
                 const __grid_constant__ CUtensorMap tmap) {
    extern __shared__ unsigned char smem_raw[];
    uint2* sB  = reinterpret_cast<uint2*>(smem_raw + SB_OFF);
    float* sc2 = reinterpret_cast<float*>(smem_raw + SC2_OFF);
    float* swp = reinterpret_cast<float*>(smem_raw + SWP_OFF);

    int tid = threadIdx.x;
    int warp = tid >> 5, lane = tid & 31;
    int g = lane >> 2, tig = lane & 3;
    int row_base = blockIdx.x * ROWS_CTA;

    unsigned sbase;
    asm("{ .reg .u64 t; cvta.to.shared.u64 t, %1; cvt.u32.u64 %0, t; }"
        : "=r"(sbase) : "l"(smem_raw));
    unsigned mbF = sbase + MB_OFF;          // full[5]
    unsigned mbE = sbase + MB_OFF + 40;     // empty[5]

    // ---- init barriers + launch prologue TMA (x DRAM stream starts FIRST) ----
    if (tid == 0) {
        #pragma unroll
        for (int s = 0; s < X_STAGES; s++) {
            mbar_init(mbF + s * 8, 1);
            mbar_init(mbE + s * 8, NWARP);
        }
        asm volatile("fence.proxy.async.shared::cta;" ::: "memory");
        #pragma unroll
        for (int j = 0; j < 4; j++) {      // first use of slots 0..3: no empty-wait
            unsigned st = sbase + j * X_STAGE_BYTES;
            mbar_expect_tx(mbF + j * 8, 32768u);
            tma2d(st,         &tmap, j * 16, row_base,       mbF + j * 8);
            tma2d(st + 16384, &tmap, j * 16, row_base + 256, mbF + j * 8);
        }
    }

    // ---- inline B-fragment build (k-permutation layout) + c2, overlapped ----
    #pragma unroll
    for (int i = 0; i < 16; i++) {
        int id = tid + i * 512;
        int bl2 = id & 31, nt = (id >> 5) & 7, ks = id >> 8;
        int n  = nt * 8 + (bl2 >> 2);
        int kb = ks * 16 + (bl2 & 3) * 4;
        float4 v = *reinterpret_cast<const float4*>(cent + n * D_EMBED + kb);
        uint2 r;
        r.x = pack_bf16(v.x, v.y);
        r.y = pack_bf16(v.z, v.w);
        sB[id] = r;
    }
    {   // c2: warp w -> centroid rows 4w..4w+3
        #pragma unroll
        for (int j = 0; j < 4; j++) {
            int r = warp * 4 + j;
            const float* c = cent + r * D_EMBED;
            float s = 0.f;
            #pragma unroll
            for (int i = 0; i < D_EMBED / 32; i++) {
                float v = c[i * 32 + lane];
                s = fmaf(v, v, s);
            }
            #pragma unroll
            for (int m = 16; m; m >>= 1) s += __shfl_xor_sync(0xffffffffu, s, m);
            if (lane == 0) sc2[r] = s;
        }
    }
    __syncthreads();

    float acc[2][8][4];
    #pragma unroll
    for (int m = 0; m < 2; m++)
        #pragma unroll
        for (int n = 0; n < 8; n++)
            #pragma unroll
            for (int j = 0; j < 4; j++) acc[m][n][j] = 0.f;

    float xs[4] = {0.f, 0.f, 0.f, 0.f};   // x^2 partials: [m*2+h]
    const uint2* bl = sB + lane;
    // lane's x slot within a stage: rows warp*32 + {g, g+8, g+16, g+24}, 64B/row
    unsigned x_off = (unsigned)(warp * 2048 + g * 64 + tig * 16);

    for (int ks = 0; ks < 32; ks++) {
        int slot = ks % X_STAGES;

        // producer: issue stage ks+4 (slot reuse -> wait consumers of ks-1)
        if (tid == 0 && ks < 28) {
            int j = ks + 4, sl = j % X_STAGES;
            if (j >= X_STAGES) mbar_wait(mbE + sl * 8, ((unsigned)(j / X_STAGES) & 1u) ^ 1u);
            unsigned st = sbase + sl * X_STAGE_BYTES;
            mbar_expect_tx(mbF + sl * 8, 32768u);
            tma2d(st,         &tmap, j * 16, row_base,       mbF + sl * 8);
            tma2d(st + 16384, &tmap, j * 16, row_base + 256, mbF + sl * 8);
        }

        mbar_wait(mbF + slot * 8, (unsigned)(ks / X_STAGES) & 1u);

        unsigned sxs = sbase + slot * X_STAGE_BYTES + x_off;
        float4 c00 = lds128(sxs);
        float4 c01 = lds128(sxs + 512);
        float4 c10 = lds128(sxs + 1024);
        float4 c11 = lds128(sxs + 1536);

        xs[0] = fmaf(c00.x, c00.x, fmaf(c00.y, c00.y, fmaf(c00.z, c00.z, fmaf(c00.w, c00.w, xs[0]))));
        xs[1] = fmaf(c01.x, c01.x, fmaf(c01.y, c01.y, fmaf(c01.z, c01.z, fmaf(c01.w, c01.w, xs[1]))));
        xs[2] = fmaf(c10.x, c10.x, fmaf(c10.y, c10.y, fmaf(c10.z, c10.z, fmaf(c10.w, c10.w, xs[2]))));
        xs[3] = fmaf(c11.x, c11.x, fmaf(c11.y, c11.y, fmaf(c11.z, c11.z, fmaf(c11.w, c11.w, xs[3]))));

        unsigned a0m0 = pack_bf16(c00.x, c00.y), a2m0 = pack_bf16(c00.z, c00.w);
        unsigned a1m0 = pack_bf16(c01.x, c01.y), a3m0 = pack_bf16(c01.z, c01.w);
        unsigned a0m1 = pack_bf16(c10.x, c10.y), a2m1 = pack_bf16(c10.z, c10.w);
        unsigned a1m1 = pack_bf16(c11.x, c11.y), a3m1 = pack_bf16(c11.z, c11.w);

        const uint2* bk = bl + ks * 256;
        #pragma unroll
        for (int nt = 0; nt < 8; nt++) {
            uint2 b = bk[nt * 32];
            mma16816(acc[0][nt], a0m0, a1m0, a2m0, a3m0, b.x, b.y);
            mma16816(acc[1][nt], a0m1, a1m1, a2m1, a3m1, b.x, b.y);
        }

        // release the slot (one arrival per warp; release orders prior reads)
        if (lane == 0) mbar_arrive(mbE + slot * 8);
    }

    // complete x^2 across the 4-lane tig group (same rows)
    #pragma unroll
    for (int i = 0; i < 4; i++) {
        xs[i] += __shfl_xor_sync(0xffffffffu, xs[i], 1);
        xs[i] += __shfl_xor_sync(0xffffffffu, xs[i], 2);
    }

    float alpha = decode_alpha(alphap);

    // softmax shift-invariance in x^2: sum(dist*soft) = x2 + sum(t*soft), t = c2 - 2*cross
    float rowsum = 0.f;
    #pragma unroll
    for (int m = 0; m < 2; m++) {
        #pragma unroll
        for (int h = 0; h < 2; h++) {
            float dd[16];
            float tmin = 3.4e38f;
            #pragma unroll
            for (int nt = 0; nt < 8; nt++) {
                int n = nt * 8 + tig * 2;
                float t0 = sc2[n]     - 2.f * acc[m][nt][h * 2 + 0];
                float t1 = sc2[n + 1] - 2.f * acc[m][nt][h * 2 + 1];
                dd[nt * 2]     = t0;
                dd[nt * 2 + 1] = t1;
                tmin = fminf(tmin, fminf(t0, t1));
            }
            tmin = fminf(tmin, __shfl_xor_sync(0xffffffffu, tmin, 1));
            tmin = fminf(tmin, __shfl_xor_sync(0xffffffffu, tmin, 2));
            float se = 0.f, sw = 0.f;
            #pragma unroll
            for (int i = 0; i < 16; i++) {
                float e = __expf(alpha * (tmin - dd[i]));
                se += e;
                sw = fmaf(dd[i], e, sw);
            }
            se += __shfl_xor_sync(0xffffffffu, se, 1);
            se += __shfl_xor_sync(0xffffffffu, se, 2);
            sw += __shfl_xor_sync(0xffffffffu, sw, 1);
            sw += __shfl_xor_sync(0xffffffffu, sw, 2);
            rowsum += xs[m * 2 + h] + sw / se;  // identical in all 4 tig lanes
        }
    }
    // warp total (each row value duplicated 4x across tig lanes -> scale 0.25)
    #pragma unroll
    for (int m = 16; m; m >>= 1) rowsum += __shfl_xor_sync(0xffffffffu, rowsum, m);
    if (lane == 0) swp[warp] = rowsum * 0.25f;
    __syncthreads();
    if (tid == 0) {
        float s = 0.f;
        #pragma unroll
        for (int i = 0; i < NWARP; i++) s += swp[i];
        atomicAdd(&g_acc, (double)s);
        __threadfence();
        unsigned t = atomicAdd(&g_ctr, 1u);
        if (t == gridDim.x - 1) {       // last CTA: finalize + reset for graph replay
            out[0] = (float)(0.1 * g_acc / (double)Ntot);
            g_acc = 0.0;
            g_ctr = 0;
            __threadfence();
        }
    }
}

// ---------------- launch ----------------
typedef CUresult (*PFN_encodeTiled)(CUtensorMap*, CUtensorMapDataType, cuuint32_t, void*,
                                    const cuuint64_t*, const cuuint64_t*, const cuuint32_t*,
                                    const cuuint32_t*, CUtensorMapInterleave, CUtensorMapSwizzle,
                                    CUtensorMapL2promotion, CUtensorMapFloatOOBfill);

extern "C" void kernel_launch(void* const* d_in, const int* in_sizes, int n_in,
                              void* d_out, int out_size) {
    const float* x    = (const float*)d_in[0];
    const float* cent = (const float*)d_in[1];
    const void*  ap   = d_in[2];
    int N = in_sizes[0] / D_EMBED;

    static PFN_encodeTiled enc = nullptr;
    if (!enc) {
        void* fp = nullptr;
        cudaDriverEntryPointQueryResult st;
        cudaGetDriverEntryPoint("cuTensorMapEncodeTiled", &fp, cudaEnableDefault, &st);
        enc = (PFN_encodeTiled)fp;
    }

    static CUtensorMap tmap;   // CUtensorMap is 64B-aligned by its own definition
    cuuint64_t gdims[2]    = {(cuuint64_t)D_EMBED, (cuuint64_t)N};
    cuuint64_t gstrides[1] = {(cuuint64_t)D_EMBED * 4};
    cuuint32_t box[2]      = {16u, 256u};
    cuuint32_t estr[2]     = {1u, 1u};
    enc(&tmap, CU_TENSOR_MAP_DATA_TYPE_FLOAT32, 2, (void*)x,
        gdims, gstrides, box, estr,
        CU_TENSOR_MAP_INTERLEAVE_NONE, CU_TENSOR_MAP_SWIZZLE_NONE,
        CU_TENSOR_MAP_L2_PROMOTION_L2_128B, CU_TENSOR_MAP_FLOAT_OOB_FILL_NONE);

    cudaFuncSetAttribute(main_kernel, cudaFuncAttributeMaxDynamicSharedMemorySize, SMEM_BYTES);
    main_kernel<<<N / ROWS_CTA, 512, SMEM_BYTES>>>(x, cent, ap, (float*)d_out, N, tmap);
}

// round 15
// speedup vs baseline: 1.0819x; 1.0819x over previous
#include <cuda_runtime.h>
#include <cuda_bf16.h>
#include <cstdint>

#define D_EMBED 512
#define N_CLUST 64
#define X_STAGES 3
#define X_STAGE_BYTES 16384                      // 256 rows x 16 cols x 4B
#define SB_OFF (X_STAGES * X_STAGE_BYTES)        // 49152
#define SC2_OFF (SB_OFF + 65536)                 // 114688
#define SMEM_BYTES (SC2_OFF + N_CLUST * 4 + 8 * 4)

// ---------------- device scratch (no allocations allowed) ----------------
__device__ float    g_c2[N_CLUST];
__device__ double   g_acc = 0.0;
__device__ unsigned g_ctr = 0;
// B fragments, vectorized: [kstep(32)][npair(4)][lane(32)] -> uint4 = {nt=2np:(b0,b1), nt=2np+1:(b0,b1)}
__device__ __align__(16) uint4 g_bfragv[32 * 4 * 32];

// ---------------- helpers ----------------
__device__ __forceinline__ unsigned pack_bf16(float lo, float hi) {
    unsigned r;
    asm("cvt.rn.bf16x2.f32 %0, %1, %2;" : "=r"(r) : "f"(hi), "f"(lo));
    return r;
}
__device__ __forceinline__ void mma16816(float* c,
                                         unsigned a0, unsigned a1, unsigned a2, unsigned a3,
                                         unsigned b0, unsigned b1) {
    asm volatile(
        "mma.sync.aligned.m16n8k16.row.col.f32.bf16.bf16.f32 "
        "{%0,%1,%2,%3}, {%4,%5,%6,%7}, {%8,%9}, {%0,%1,%2,%3};"
        : "+f"(c[0]), "+f"(c[1]), "+f"(c[2]), "+f"(c[3])
        : "r"(a0), "r"(a1), "r"(a2), "r"(a3), "r"(b0), "r"(b1));
}
__device__ __forceinline__ void cp16(unsigned dst, const float* src) {
    asm volatile("cp.async.cg.shared.global [%0], [%1], 16;" :: "r"(dst), "l"(src));
}
__device__ __forceinline__ void pf_l2(const float* p) {
    asm volatile("prefetch.global.L2 [%0];" :: "l"(p));
}
#define CP_COMMIT() asm volatile("cp.async.commit_group;" ::: "memory")
#define CP_WAIT2()  asm volatile("cp.async.wait_group 2;" ::: "memory")

// alpha may arrive as int32 / int64 / float32 (python scalar 100). Decode robustly.
__device__ __forceinline__ float decode_alpha(const void* p) {
    int iv = *reinterpret_cast<const int*>(p);
    unsigned u = (unsigned)iv;
    unsigned ex = (u >> 23) & 0xffu;
    if (ex >= 110u && ex <= 150u) return __int_as_float(iv);
    if (iv == 0) {
        double dv = *reinterpret_cast<const double*>(p);
        if (dv > 1e-6 && dv < 1e9) return (float)dv;
    }
    return (float)iv;
}

// ---------------- kernel 1: fused setup (c2 + vectorized bf16 B-fragments) ----------------
// k-permutation: logical k-pairs of the m16n8k16 B fragment map to physical
// columns (tig*4+{0,1})/(tig*4+{2,3}) so the A side consumes one float4.
__global__ void setup_kernel(const float* __restrict__ cent) {
    int id = blockIdx.x * blockDim.x + threadIdx.x;   // 0..4095
    {
        int lane = id & 31, np = (id >> 5) & 3, ks = id >> 7;
        int kb = ks * 16 + (lane & 3) * 4;
        int n0 = (2 * np) * 8 + (lane >> 2);
        int n1 = (2 * np + 1) * 8 + (lane >> 2);
        float4 v0 = *reinterpret_cast<const float4*>(cent + n0 * D_EMBED + kb);
        float4 v1 = *reinterpret_cast<const float4*>(cent + n1 * D_EMBED + kb);
        uint4 r;
        r.x = pack_bf16(v0.x, v0.y);
        r.y = pack_bf16(v0.z, v0.w);
        r.z = pack_bf16(v1.x, v1.y);
        r.w = pack_bf16(v1.z, v1.w);
        g_bfragv[id] = r;
    }
    if (id < N_CLUST * 32) {
        int w = id >> 5, lane = id & 31;
        const float* c = cent + w * D_EMBED;
        float s = 0.f;
        #pragma unroll
        for (int i = 0; i < D_EMBED / 32; i++) {
            float v = c[i * 32 + lane];
            s = fmaf(v, v, s);
        }
        #pragma unroll
        for (int m = 16; m; m >>= 1) s += __shfl_xor_sync(0xffffffffu, s, m);
        if (lane == 0) g_c2[w] = s;
    }
}

// ---------------- kernel 2: main fused GEMM + softmax + finalize ----------------
__global__ __launch_bounds__(256, 2)
void main_kernel(const float* __restrict__ x, const void* __restrict__ alphap,
                 float* __restrict__ out, int Ntot) {
    extern __shared__ unsigned char smem_raw[];
    uint4* sB  = reinterpret_cast<uint4*>(smem_raw + SB_OFF);
    float* sc2 = reinterpret_cast<float*>(smem_raw + SC2_OFF);
    float* swp = sc2 + N_CLUST;

    int tid = threadIdx.x;
    {
        const uint4* src = g_bfragv;
        #pragma unroll
        for (int i = 0; i < 16; i++) sB[i * 256 + tid] = src[i * 256 + tid];
        if (tid < N_CLUST) sc2[tid] = g_c2[tid];
    }
    __syncthreads();

    int warp = tid >> 5, lane = tid & 31;
    int g = lane >> 2, tig = lane & 3;
    size_t base = (size_t)blockIdx.x * 256 + (size_t)warp * 32;
    // lane's gmem streams: rows base+g (+8/+16/+24), cols tig*4 + ks*16
    const float* xr = x + (base + g) * D_EMBED + tig * 4;

    // per-warp private smem x slots: [stage][warp][j][lane] 16B each
    unsigned sx_lane;
    {
        unsigned sbase;
        asm("{ .reg .u64 t; cvta.to.shared.u64 t, %1; cvt.u32.u64 %0, t; }"
            : "=r"(sbase) : "l"(smem_raw));
        sx_lane = sbase + warp * 2048 + lane * 16;
    }

    float acc[2][8][4];
    #pragma unroll
    for (int m = 0; m < 2; m++)
        #pragma unroll
        for (int n = 0; n < 8; n++)
            #pragma unroll
            for (int j = 0; j < 4; j++) acc[m][n][j] = 0.f;

    float xs[4] = {0.f, 0.f, 0.f, 0.f};  // x^2 partials: [m*2+h]
    const uint4* bl = sB + lane;

    // ---- prologue: stage ks=0 and ks=1; L2-prefetch ks=2..5 ----
    #pragma unroll
    for (int p = 0; p < 2; p++) {
        unsigned d = sx_lane + p * X_STAGE_BYTES;
        const float* s = xr + p * 16;
        cp16(d,        s);                 // rows base+g
        cp16(d + 512,  s + 8  * D_EMBED);  // rows base+g+8
        cp16(d + 1024, s + 16 * D_EMBED);  // rows base+g+16
        cp16(d + 1536, s + 24 * D_EMBED);  // rows base+g+24
        CP_COMMIT();
    }
    if (tig == 0) {
        #pragma unroll
        for (int p = 2; p < 6; p++) {
            const float* s = xr + p * 16;
            pf_l2(s); pf_l2(s + 8 * D_EMBED); pf_l2(s + 16 * D_EMBED); pf_l2(s + 24 * D_EMBED);
        }
    }

    for (int ks = 0; ks < 32; ks++) {
        // stage ks+2 from L2 (empty commit in tail keeps wait numbering exact)
        if (ks < 30) {
            unsigned d = sx_lane + ((ks + 2) % X_STAGES) * X_STAGE_BYTES;
            const float* s = xr + (ks + 2) * 16;
            cp16(d,        s);
            cp16(d + 512,  s + 8  * D_EMBED);
            cp16(d + 1024, s + 16 * D_EMBED);
            cp16(d + 1536, s + 24 * D_EMBED);
        }
        CP_COMMIT();
        // L2 prefetch ks+6 (one lane per tig-group; lines dedup in L2)
        if (ks < 26 && tig == 0) {
            const float* s = xr + (ks + 6) * 16;
            pf_l2(s); pf_l2(s + 8 * D_EMBED); pf_l2(s + 16 * D_EMBED); pf_l2(s + 24 * D_EMBED);
        }
        CP_WAIT2();  // group for ks is complete

        unsigned sxs = sx_lane + (ks % X_STAGES) * X_STAGE_BYTES;
        float4 c00, c01, c10, c11;
        asm volatile("ld.shared.v4.f32 {%0,%1,%2,%3}, [%4];"
                     : "=f"(c00.x), "=f"(c00.y), "=f"(c00.z), "=f"(c00.w) : "r"(sxs));
        asm volatile("ld.shared.v4.f32 {%0,%1,%2,%3}, [%4];"
                     : "=f"(c01.x), "=f"(c01.y), "=f"(c01.z), "=f"(c01.w) : "r"(sxs + 512));
        asm volatile("ld.shared.v4.f32 {%0,%1,%2,%3}, [%4];"
                     : "=f"(c10.x), "=f"(c10.y), "=f"(c10.z), "=f"(c10.w) : "r"(sxs + 1024));
        asm volatile("ld.shared.v4.f32 {%0,%1,%2,%3}, [%4];"
                     : "=f"(c11.x), "=f"(c11.y), "=f"(c11.z), "=f"(c11.w) : "r"(sxs + 1536));

        xs[0] = fmaf(c00.x, c00.x, fmaf(c00.y, c00.y, fmaf(c00.z, c00.z, fmaf(c00.w, c00.w, xs[0]))));
        xs[1] = fmaf(c01.x, c01.x, fmaf(c01.y, c01.y, fmaf(c01.z, c01.z, fmaf(c01.w, c01.w, xs[1]))));
        xs[2] = fmaf(c10.x, c10.x, fmaf(c10.y, c10.y, fmaf(c10.z, c10.z, fmaf(c10.w, c10.w, xs[2]))));
        xs[3] = fmaf(c11.x, c11.x, fmaf(c11.y, c11.y, fmaf(c11.z, c11.z, fmaf(c11.w, c11.w, xs[3]))));

        unsigned a0m0 = pack_bf16(c00.x, c00.y), a2m0 = pack_bf16(c00.z, c00.w);
        unsigned a1m0 = pack_bf16(c01.x, c01.y), a3m0 = pack_bf16(c01.z, c01.w);
        unsigned a0m1 = pack_bf16(c10.x, c10.y), a2m1 = pack_bf16(c10.z, c10.w);
        unsigned a1m1 = pack_bf16(c11.x, c11.y), a3m1 = pack_bf16(c11.z, c11.w);

        const uint4* bk = bl + ks * 128;
        #pragma unroll
        for (int np = 0; np < 4; np++) {
            uint4 b = bk[np * 32];
            mma16816(acc[0][2 * np],     a0m0, a1m0, a2m0, a3m0, b.x, b.y);
            mma16816(acc[0][2 * np + 1], a0m0, a1m0, a2m0, a3m0, b.z, b.w);
            mma16816(acc[1][2 * np],     a0m1, a1m1, a2m1, a3m1, b.x, b.y);
            mma16816(acc[1][2 * np + 1], a0m1, a1m1, a2m1, a3m1, b.z, b.w);
        }
    }

    // complete x^2 across the 4-lane tig group (same rows)
    #pragma unroll
    for (int i = 0; i < 4; i++) {
        xs[i] += __shfl_xor_sync(0xffffffffu, xs[i], 1);
        xs[i] += __shfl_xor_sync(0xffffffffu, xs[i], 2);
    }

    float alpha = decode_alpha(alphap);

    // softmax shift-invariance in x^2: sum(dist*soft) = x2 + sum(t*soft), t = c2 - 2*cross
    float rowsum = 0.f;
    #pragma unroll
    for (int m = 0; m < 2; m++) {
        #pragma unroll
        for (int h = 0; h < 2; h++) {
            float dd[16];
            float tmin = 3.4e38f;
            #pragma unroll
            for (int nt = 0; nt < 8; nt++) {
                int n = nt * 8 + tig * 2;
                float t0 = sc2[n]     - 2.f * acc[m][nt][h * 2 + 0];
                float t1 = sc2[n + 1] - 2.f * acc[m][nt][h * 2 + 1];
                dd[nt * 2]     = t0;
                dd[nt * 2 + 1] = t1;
                tmin = fminf(tmin, fminf(t0, t1));
            }
            tmin = fminf(tmin, __shfl_xor_sync(0xffffffffu, tmin, 1));
            tmin = fminf(tmin, __shfl_xor_sync(0xffffffffu, tmin, 2));
            float se = 0.f, sw = 0.f;
            #pragma unroll
            for (int i = 0; i < 16; i++) {
                float e = __expf(alpha * (tmin - dd[i]));
                se += e;
                sw = fmaf(dd[i], e, sw);
            }
            se += __shfl_xor_sync(0xffffffffu, se, 1);
            se += __shfl_xor_sync(0xffffffffu, se, 2);
            sw += __shfl_xor_sync(0xffffffffu, sw, 1);
            sw += __shfl_xor_sync(0xffffffffu, sw, 2);
            rowsum += xs[m * 2 + h] + sw / se;  // identical in all 4 tig lanes
        }
    }
    // warp total (each row value duplicated 4x across tig lanes -> scale 0.25)
    #pragma unroll
    for (int m = 16; m; m >>= 1) rowsum += __shfl_xor_sync(0xffffffffu, rowsum, m);
    if (lane == 0) swp[warp] = rowsum * 0.25f;
    __syncthreads();
    if (tid == 0) {
        float s = 0.f;
        #pragma unroll
        for (int i = 0; i < 8; i++) s += swp[i];
        atomicAdd(&g_acc, (double)s);
        __threadfence();
        unsigned t = atomicAdd(&g_ctr, 1u);
        if (t == gridDim.x - 1) {       // last CTA: finalize + reset for graph replay
            out[0] = (float)(0.1 * g_acc / (double)Ntot);
            g_acc = 0.0;
            g_ctr = 0;
            __threadfence();
        }
    }
}

// ---------------- launch ----------------
extern "C" void kernel_launch(void* const* d_in, const int* in_sizes, int n_in,
                              void* d_out, int out_size) {
    const float* x    = (const float*)d_in[0];
    const float* cent = (const float*)d_in[1];
    const void*  ap   = d_in[2];
    int N = in_sizes[0] / D_EMBED;

    cudaFuncSetAttribute(main_kernel, cudaFuncAttributeMaxDynamicSharedMemorySize, SMEM_BYTES);

    setup_kernel<<<16, 256>>>(cent);
    main_kernel<<<N / 256, 256, SMEM_BYTES>>>(x, ap, (float*)d_out, N);
}

// round 16
// speedup vs baseline: 1.1435x; 1.0569x over previous
#include <cuda_runtime.h>
#include <cuda_bf16.h>
#include <cstdint>

#define D_EMBED 512
#define N_CLUST 64
#define RB 128                                   // rows per block
#define GRID_CTAS 296                            // 2 per SM x 148 SMs
#define STG_BYTES 8192                           // stage: 8 warps x 16 rows x 64B
#define SB_OFF (3 * STG_BYTES)                   // 24576
#define SC2_OFF (SB_OFF + 65536)                 // 90112
#define SWP_OFF (SC2_OFF + 256)                  // 90368
#define SMEM_BYTES (SWP_OFF + 32)                // 90400

// ---------------- device scratch (no allocations allowed) ----------------
__device__ double   g_acc = 0.0;
__device__ unsigned g_ctr = 0;

// ---------------- helpers ----------------
__device__ __forceinline__ unsigned pack_bf16(float lo, float hi) {
    unsigned r;
    asm("cvt.rn.bf16x2.f32 %0, %1, %2;" : "=r"(r) : "f"(hi), "f"(lo));
    return r;
}
__device__ __forceinline__ void mma16816(float* c,
                                         unsigned a0, unsigned a1, unsigned a2, unsigned a3,
                                         unsigned b0, unsigned b1) {
    asm volatile(
        "mma.sync.aligned.m16n8k16.row.col.f32.bf16.bf16.f32 "
        "{%0,%1,%2,%3}, {%4,%5,%6,%7}, {%8,%9}, {%0,%1,%2,%3};"
        : "+f"(c[0]), "+f"(c[1]), "+f"(c[2]), "+f"(c[3])
        : "r"(a0), "r"(a1), "r"(a2), "r"(a3), "r"(b0), "r"(b1));
}
__device__ __forceinline__ void cp16(unsigned dst, const float* src) {
    asm volatile("cp.async.cg.shared.global [%0], [%1], 16;" :: "r"(dst), "l"(src));
}
#define CP_COMMIT() asm volatile("cp.async.commit_group;" ::: "memory")
#define CP_WAIT2()  asm volatile("cp.async.wait_group 2;" ::: "memory")
__device__ __forceinline__ float4 lds128(unsigned addr) {
    float4 v;
    asm volatile("ld.shared.v4.f32 {%0,%1,%2,%3}, [%4];"
                 : "=f"(v.x), "=f"(v.y), "=f"(v.z), "=f"(v.w) : "r"(addr));
    return v;
}

// alpha may arrive as int32 / int64 / float32 (python scalar 100). Decode robustly.
__device__ __forceinline__ float decode_alpha(const void* p) {
    int iv = *reinterpret_cast<const int*>(p);
    unsigned u = (unsigned)iv;
    unsigned ex = (u >> 23) & 0xffu;
    if (ex >= 110u && ex <= 150u) return __int_as_float(iv);
    if (iv == 0) {
        double dv = *reinterpret_cast<const double*>(p);
        if (dv > 1e-6 && dv < 1e9) return (float)dv;
    }
    return (float)iv;
}

// ---------------- single persistent kernel ----------------
__global__ __launch_bounds__(256, 2)
void main_kernel(const float* __restrict__ x, const float* __restrict__ cent,
                 const void* __restrict__ alphap, float* __restrict__ out,
                 int Ntot, int NBLK) {
    extern __shared__ unsigned char smem_raw[];
    uint4* sB  = reinterpret_cast<uint4*>(smem_raw + SB_OFF);
    float* sc2 = reinterpret_cast<float*>(smem_raw + SC2_OFF);
    float* swp = reinterpret_cast<float*>(smem_raw + SWP_OFF);

    int tid = threadIdx.x;
    int warp = tid >> 5, lane = tid & 31;
    int g = lane >> 2, tig = lane & 3;
    int bid = blockIdx.x;
    int stride = gridDim.x;
    int nmy = (NBLK - 1 - bid) / stride + 1;     // blocks this CTA owns
    int nit = nmy * 32;

    unsigned sx_lane;
    {
        unsigned sbase;
        asm("{ .reg .u64 t; cvta.to.shared.u64 t, %1; cvt.u32.u64 %0, t; }"
            : "=r"(sbase) : "l"(smem_raw));
        sx_lane = sbase + warp * 1024 + lane * 16;   // slot within a stage
    }

    // ---- stage flat-iteration j: block j>>5, kstep j&31, ring slot j%3 ----
    #define STAGE(j) do {                                                        \
        int _blk = (j) >> 5, _ks = (j) & 31;                                     \
        size_t _row = ((size_t)bid + (size_t)_blk * stride) * RB + warp * 16 + g;\
        const float* _s = x + _row * D_EMBED + _ks * 16 + tig * 4;               \
        unsigned _d = sx_lane + (unsigned)(((j) % 3) * STG_BYTES);               \
        cp16(_d, _s);                                                            \
        cp16(_d + 512, _s + 8 * D_EMBED);                                        \
    } while (0)

    // prologue: DRAM stream starts before B build
    STAGE(0); CP_COMMIT();
    STAGE(1); CP_COMMIT();

    // ---- inline B-fragment build (vectorized k-permutation layout) ----
    // entry id: lane=id&31, np=(id>>5)&3, ks=id>>7 -> uint4 {nt=2np:(b0,b1), nt=2np+1:(b0,b1)}
    #pragma unroll
    for (int i = 0; i < 16; i++) {
        int id = tid + i * 256;
        int bl2 = id & 31, np = (id >> 5) & 3, ks = id >> 7;
        int kb = ks * 16 + (bl2 & 3) * 4;
        int n0 = (2 * np) * 8 + (bl2 >> 2);
        int n1 = (2 * np + 1) * 8 + (bl2 >> 2);
        float4 v0 = *reinterpret_cast<const float4*>(cent + n0 * D_EMBED + kb);
        float4 v1 = *reinterpret_cast<const float4*>(cent + n1 * D_EMBED + kb);
        uint4 r;
        r.x = pack_bf16(v0.x, v0.y);
        r.y = pack_bf16(v0.z, v0.w);
        r.z = pack_bf16(v1.x, v1.y);
        r.w = pack_bf16(v1.z, v1.w);
        sB[id] = r;
    }
    {   // c2: warp w -> centroid rows 8w..8w+7
        #pragma unroll
        for (int j = 0; j < 8; j++) {
            int r = warp * 8 + j;
            const float* c = cent + r * D_EMBED;
            float s = 0.f;
            #pragma unroll
            for (int i = 0; i < D_EMBED / 32; i++) {
                float v = c[i * 32 + lane];
                s = fmaf(v, v, s);
            }
            #pragma unroll
            for (int m = 16; m; m >>= 1) s += __shfl_xor_sync(0xffffffffu, s, m);
            if (lane == 0) sc2[r] = s;
        }
    }
    __syncthreads();

    float alpha = decode_alpha(alphap);

    float acc[8][4];
    #pragma unroll
    for (int n = 0; n < 8; n++)
        #pragma unroll
        for (int j = 0; j < 4; j++) acc[n][j] = 0.f;
    float xs0 = 0.f, xs1 = 0.f;
    float block_sum = 0.f;
    const uint4* bl = sB + lane;

    for (int it = 0; it < nit; it++) {
        if (it + 2 < nit) STAGE(it + 2);
        CP_COMMIT();            // empty group in tail keeps wait numbering exact
        CP_WAIT2();             // group 'it' complete

        int ks = it & 31;
        unsigned sxs = sx_lane + (unsigned)((it % 3) * STG_BYTES);
        float4 c0 = lds128(sxs);         // row warp*16+g
        float4 c1 = lds128(sxs + 512);   // row warp*16+g+8

        xs0 = fmaf(c0.x, c0.x, fmaf(c0.y, c0.y, fmaf(c0.z, c0.z, fmaf(c0.w, c0.w, xs0))));
        xs1 = fmaf(c1.x, c1.x, fmaf(c1.y, c1.y, fmaf(c1.z, c1.z, fmaf(c1.w, c1.w, xs1))));

        unsigned a0 = pack_bf16(c0.x, c0.y), a2 = pack_bf16(c0.z, c0.w);
        unsigned a1 = pack_bf16(c1.x, c1.y), a3 = pack_bf16(c1.z, c1.w);

        const uint4* bk = bl + ks * 128;
        #pragma unroll
        for (int np = 0; np < 4; np++) {
            uint4 b = bk[np * 32];
            mma16816(acc[2 * np],     a0, a1, a2, a3, b.x, b.y);
            mma16816(acc[2 * np + 1], a0, a1, a2, a3, b.z, b.w);
        }

        if (ks == 31) {
            // complete x^2 across the 4-lane tig group (same rows)
            xs0 += __shfl_xor_sync(0xffffffffu, xs0, 1);
            xs0 += __shfl_xor_sync(0xffffffffu, xs0, 2);
            xs1 += __shfl_xor_sync(0xffffffffu, xs1, 1);
            xs1 += __shfl_xor_sync(0xffffffffu, xs1, 2);

            // softmax shift-invariance: sum(dist*soft) = x2 + sum(t*soft), t = c2 - 2*cross
            #pragma unroll
            for (int h = 0; h < 2; h++) {
                float dd[16];
                float tmin = 3.4e38f;
                #pragma unroll
                for (int nt = 0; nt < 8; nt++) {
                    int n = nt * 8 + tig * 2;
                    float t0 = sc2[n]     - 2.f * acc[nt][h * 2 + 0];
                    float t1 = sc2[n + 1] - 2.f * acc[nt][h * 2 + 1];
                    dd[nt * 2]     = t0;
                    dd[nt * 2 + 1] = t1;
                    tmin = fminf(tmin, fminf(t0, t1));
                }
                tmin = fminf(tmin, __shfl_xor_sync(0xffffffffu, tmin, 1));
                tmin = fminf(tmin, __shfl_xor_sync(0xffffffffu, tmin, 2));
                float se = 0.f, sw = 0.f;
                #pragma unroll
                for (int i = 0; i < 16; i++) {
                    float e = __expf(alpha * (tmin - dd[i]));
                    se += e;
                    sw = fmaf(dd[i], e, sw);
                }
                se += __shfl_xor_sync(0xffffffffu, se, 1);
                se += __shfl_xor_sync(0xffffffffu, se, 2);
                sw += __shfl_xor_sync(0xffffffffu, sw, 1);
                sw += __shfl_xor_sync(0xffffffffu, sw, 2);
                block_sum += (h == 0 ? xs0 : xs1) + sw / se;  // same in all 4 tig lanes
            }
            // reset per-block state
            #pragma unroll
            for (int n = 0; n < 8; n++)
                #pragma unroll
                for (int j = 0; j < 4; j++) acc[n][j] = 0.f;
            xs0 = 0.f;
            xs1 = 0.f;
        }
    }

    // warp total (each row value duplicated 4x across tig lanes -> scale 0.25)
    #pragma unroll
    for (int m = 16; m; m >>= 1) block_sum += __shfl_xor_sync(0xffffffffu, block_sum, m);
    if (lane == 0) swp[warp] = block_sum * 0.25f;
    __syncthreads();
    if (tid == 0) {
        float s = 0.f;
        #pragma unroll
        for (int i = 0; i < 8; i++) s += swp[i];
        atomicAdd(&g_acc, (double)s);
        __threadfence();
        unsigned t = atomicAdd(&g_ctr, 1u);
        if (t == gridDim.x - 1) {       // last CTA: finalize + reset for graph replay
            out[0] = (float)(0.1 * g_acc / (double)Ntot);
            g_acc = 0.0;
            g_ctr = 0;
            __threadfence();
        }
    }
    #undef STAGE
}

// ---------------- launch ----------------
extern "C" void kernel_launch(void* const* d_in, const int* in_sizes, int n_in,
                              void* d_out, int out_size) {
    const float* x    = (const float*)d_in[0];
    const float* cent = (const float*)d_in[1];
    const void*  ap   = d_in[2];
    int N = in_sizes[0] / D_EMBED;
    int NBLK = N / RB;
    int grid = NBLK < GRID_CTAS ? NBLK : GRID_CTAS;

    cudaFuncSetAttribute(main_kernel, cudaFuncAttributeMaxDynamicSharedMemorySize, SMEM_BYTES);
    main_kernel<<<grid, 256, SMEM_BYTES>>>(x, cent, ap, (float*)d_out, N, NBLK);
}

// round 17
// speedup vs baseline: 1.2284x; 1.0743x over previous
#include <cuda_runtime.h>
#include <cuda_bf16.h>
#include <cstdint>

#define D_EMBED 512
#define N_CLUST 64
#define RB 128                                   // rows per block
#define GRID_CTAS 296                            // 2 per SM x 148 SMs
#define STG_BYTES 8192                           // stage: 8 warps x 16 rows x 64B
#define SB_OFF (4 * STG_BYTES)                   // 32768
#define SC2_OFF (SB_OFF + 65536)                 // 98304
#define SWP_OFF (SC2_OFF + 256)                  // 98560
#define SMEM_BYTES (SWP_OFF + 32)                // 98592

// ---------------- device scratch (no allocations allowed) ----------------
__device__ double   g_acc = 0.0;
__device__ unsigned g_ctr = 0;

// ---------------- helpers ----------------
__device__ __forceinline__ unsigned pack_bf16(float lo, float hi) {
    unsigned r;
    asm("cvt.rn.bf16x2.f32 %0, %1, %2;" : "=r"(r) : "f"(hi), "f"(lo));
    return r;
}
__device__ __forceinline__ void mma16816(float* c,
                                         unsigned a0, unsigned a1, unsigned a2, unsigned a3,
                                         unsigned b0, unsigned b1) {
    asm volatile(
        "mma.sync.aligned.m16n8k16.row.col.f32.bf16.bf16.f32 "
        "{%0,%1,%2,%3}, {%4,%5,%6,%7}, {%8,%9}, {%0,%1,%2,%3};"
        : "+f"(c[0]), "+f"(c[1]), "+f"(c[2]), "+f"(c[3])
        : "r"(a0), "r"(a1), "r"(a2), "r"(a3), "r"(b0), "r"(b1));
}
__device__ __forceinline__ void cp16(unsigned dst, const float* src) {
    asm volatile("cp.async.cg.shared.global [%0], [%1], 16;" :: "r"(dst), "l"(src));
}
#define CP_COMMIT() asm volatile("cp.async.commit_group;" ::: "memory")
#define CP_WAIT3()  asm volatile("cp.async.wait_group 3;" ::: "memory")
__device__ __forceinline__ float4 lds128(unsigned addr) {
    float4 v;
    asm volatile("ld.shared.v4.f32 {%0,%1,%2,%3}, [%4];"
                 : "=f"(v.x), "=f"(v.y), "=f"(v.z), "=f"(v.w) : "r"(addr));
    return v;
}

// alpha may arrive as int32 / int64 / float32 (python scalar 100). Decode robustly.
__device__ __forceinline__ float decode_alpha(const void* p) {
    int iv = *reinterpret_cast<const int*>(p);
    unsigned u = (unsigned)iv;
    unsigned ex = (u >> 23) & 0xffu;
    if (ex >= 110u && ex <= 150u) return __int_as_float(iv);
    if (iv == 0) {
        double dv = *reinterpret_cast<const double*>(p);
        if (dv > 1e-6 && dv < 1e9) return (float)dv;
    }
    return (float)iv;
}

// ---------------- single persistent kernel ----------------
__global__ __launch_bounds__(256, 2)
void main_kernel(const float* __restrict__ x, const float* __restrict__ cent,
                 const void* __restrict__ alphap, float* __restrict__ out,
                 int Ntot, int NBLK) {
    extern __shared__ unsigned char smem_raw[];
    uint4* sB  = reinterpret_cast<uint4*>(smem_raw + SB_OFF);
    float* sc2 = reinterpret_cast<float*>(smem_raw + SC2_OFF);
    float* swp = reinterpret_cast<float*>(smem_raw + SWP_OFF);

    int tid = threadIdx.x;
    int warp = tid >> 5, lane = tid & 31;
    int g = lane >> 2, tig = lane & 3;
    int bid = blockIdx.x;
    int stride = gridDim.x;
    int nmy = (NBLK - 1 - bid) / stride + 1;     // blocks this CTA owns

    unsigned sx_lane;
    {
        unsigned sbase;
        asm("{ .reg .u64 t; cvta.to.shared.u64 t, %1; cvt.u32.u64 %0, t; }"
            : "=r"(sbase) : "l"(smem_raw));
        sx_lane = sbase + warp * 1024 + lane * 16;   // slot within a stage
    }

    // lane's base pointer for its first block; blocks step by stride*RB rows
    const float* xcur = x + ((size_t)bid * RB + warp * 16 + g) * D_EMBED + tig * 4;
    const size_t blkstep = (size_t)stride * RB * D_EMBED;
    const float* xnxt = xcur + blkstep;

    // ---- prologue: stage ks=0,1,2 of block 0 (DRAM stream starts before B build) ----
    #pragma unroll
    for (int p = 0; p < 3; p++) {
        unsigned d = sx_lane + (unsigned)(p * STG_BYTES);
        cp16(d,       xcur + p * 16);
        cp16(d + 512, xcur + p * 16 + 8 * D_EMBED);
        CP_COMMIT();
    }

    // ---- inline B-fragment build (vectorized k-permutation layout) ----
    #pragma unroll
    for (int i = 0; i < 16; i++) {
        int id = tid + i * 256;
        int bl2 = id & 31, np = (id >> 5) & 3, ks = id >> 7;
        int kb = ks * 16 + (bl2 & 3) * 4;
        int n0 = (2 * np) * 8 + (bl2 >> 2);
        int n1 = (2 * np + 1) * 8 + (bl2 >> 2);
        float4 v0 = *reinterpret_cast<const float4*>(cent + n0 * D_EMBED + kb);
        float4 v1 = *reinterpret_cast<const float4*>(cent + n1 * D_EMBED + kb);
        uint4 r;
        r.x = pack_bf16(v0.x, v0.y);
        r.y = pack_bf16(v0.z, v0.w);
        r.z = pack_bf16(v1.x, v1.y);
        r.w = pack_bf16(v1.z, v1.w);
        sB[id] = r;
    }
    {   // c2: warp w -> centroid rows 8w..8w+7
        #pragma unroll
        for (int j = 0; j < 8; j++) {
            int r = warp * 8 + j;
            const float* c = cent + r * D_EMBED;
            float s = 0.f;
            #pragma unroll
            for (int i = 0; i < D_EMBED / 32; i++) {
                float v = c[i * 32 + lane];
                s = fmaf(v, v, s);
            }
            #pragma unroll
            for (int m = 16; m; m >>= 1) s += __shfl_xor_sync(0xffffffffu, s, m);
            if (lane == 0) sc2[r] = s;
        }
    }
    __syncthreads();

    float alpha = decode_alpha(alphap);
    const uint4* bl = sB + lane;
    float cta_sum = 0.f;

    for (int blk = 0; blk < nmy; blk++) {
        bool last = (blk == nmy - 1);

        float acc[8][4];
        #pragma unroll
        for (int n = 0; n < 8; n++)
            #pragma unroll
            for (int j = 0; j < 4; j++) acc[n][j] = 0.f;
        float xs0 = 0.f, xs1 = 0.f;

        #pragma unroll 4
        for (int ks = 0; ks < 32; ks++) {
            // stage flat-iter +3; slot (ks+3)&3 (32 = 0 mod 4 -> consistent across blocks)
            {
                int js = ks + 3;
                bool wrap = js >= 32;
                if (!(last && wrap)) {
                    const float* sp = wrap ? xnxt + (js - 32) * 16 : xcur + js * 16;
                    unsigned d = sx_lane + (unsigned)((js & 3) * STG_BYTES);
                    cp16(d,       sp);
                    cp16(d + 512, sp + 8 * D_EMBED);
                }
            }
            CP_COMMIT();     // empty group in tail keeps wait numbering exact
            CP_WAIT3();      // group for this iteration is complete

            unsigned sxs = sx_lane + (unsigned)((ks & 3) * STG_BYTES);
            float4 c0 = lds128(sxs);         // row warp*16+g
            float4 c1 = lds128(sxs + 512);   // row warp*16+g+8

            xs0 = fmaf(c0.x, c0.x, fmaf(c0.y, c0.y, fmaf(c0.z, c0.z, fmaf(c0.w, c0.w, xs0))));
            xs1 = fmaf(c1.x, c1.x, fmaf(c1.y, c1.y, fmaf(c1.z, c1.z, fmaf(c1.w, c1.w, xs1))));

            unsigned a0 = pack_bf16(c0.x, c0.y), a2 = pack_bf16(c0.z, c0.w);
            unsigned a1 = pack_bf16(c1.x, c1.y), a3 = pack_bf16(c1.z, c1.w);

            const uint4* bk = bl + ks * 128;
            #pragma unroll
            for (int np = 0; np < 4; np++) {
                uint4 b = bk[np * 32];
                mma16816(acc[2 * np],     a0, a1, a2, a3, b.x, b.y);
                mma16816(acc[2 * np + 1], a0, a1, a2, a3, b.z, b.w);
            }
        }

        // ---- per-block epilogue (out of hot loop) ----
        xs0 += __shfl_xor_sync(0xffffffffu, xs0, 1);
        xs0 += __shfl_xor_sync(0xffffffffu, xs0, 2);
        xs1 += __shfl_xor_sync(0xffffffffu, xs1, 1);
        xs1 += __shfl_xor_sync(0xffffffffu, xs1, 2);

        // softmax shift-invariance: sum(dist*soft) = x2 + sum(t*soft), t = c2 - 2*cross
        #pragma unroll
        for (int h = 0; h < 2; h++) {
            float dd[16];
            float tmin = 3.4e38f;
            #pragma unroll
            for (int nt = 0; nt < 8; nt++) {
                int n = nt * 8 + tig * 2;
                float t0 = sc2[n]     - 2.f * acc[nt][h * 2 + 0];
                float t1 = sc2[n + 1] - 2.f * acc[nt][h * 2 + 1];
                dd[nt * 2]     = t0;
                dd[nt * 2 + 1] = t1;
                tmin = fminf(tmin, fminf(t0, t1));
            }
            tmin = fminf(tmin, __shfl_xor_sync(0xffffffffu, tmin, 1));
            tmin = fminf(tmin, __shfl_xor_sync(0xffffffffu, tmin, 2));
            float se = 0.f, sw = 0.f;
            #pragma unroll
            for (int i = 0; i < 16; i++) {
                float e = __expf(alpha * (tmin - dd[i]));
                se += e;
                sw = fmaf(dd[i], e, sw);
            }
            se += __shfl_xor_sync(0xffffffffu, se, 1);
            se += __shfl_xor_sync(0xffffffffu, se, 2);
            sw += __shfl_xor_sync(0xffffffffu, sw, 1);
            sw += __shfl_xor_sync(0xffffffffu, sw, 2);
            cta_sum += (h == 0 ? xs0 : xs1) + sw / se;   // same in all 4 tig lanes
        }

        xcur = xnxt;
        xnxt += blkstep;
    }

    // warp total (each row value duplicated 4x across tig lanes -> scale 0.25)
    #pragma unroll
    for (int m = 16; m; m >>= 1) cta_sum += __shfl_xor_sync(0xffffffffu, cta_sum, m);
    if (lane == 0) swp[warp] = cta_sum * 0.25f;
    __syncthreads();
    if (tid == 0) {
        float s = 0.f;
        #pragma unroll
        for (int i = 0; i < 8; i++) s += swp[i];
        atomicAdd(&g_acc, (double)s);
        __threadfence();
        unsigned t = atomicAdd(&g_ctr, 1u);
        if (t == gridDim.x - 1) {       // last CTA: finalize + reset for graph replay
            out[0] = (float)(0.1 * g_acc / (double)Ntot);
            g_acc = 0.0;
            g_ctr = 0;
            __threadfence();
        }
    }
}

// ---------------- launch ----------------
extern "C" void kernel_launch(void* const* d_in, const int* in_sizes, int n_in,
                              void* d_out, int out_size) {
    const float* x    = (const float*)d_in[0];
    const float* cent = (const float*)d_in[1];
    const void*  ap   = d_in[2];
    int N = in_sizes[0] / D_EMBED;
    int NBLK = N / RB;
    int grid = NBLK < GRID_CTAS ? NBLK : GRID_CTAS;

    cudaFuncSetAttribute(main_kernel, cudaFuncAttributeMaxDynamicSharedMemorySize, SMEM_BYTES);
    main_kernel<<<grid, 256, SMEM_BYTES>>>(x, cent, ap, (float*)d_out, N, NBLK);
}